// round 3
// baseline (speedup 1.0000x reference)
#include <cuda_runtime.h>
#include <cstddef>

#define Hd 10
#define Td 20
#define M1 5

using u64 = unsigned long long;

// ---- f32x2 packed helpers (sm_100+) ----
__device__ __forceinline__ u64 pack2(float lo, float hi) {
    u64 r; asm("mov.b64 %0, {%1, %2};" : "=l"(r) : "f"(lo), "f"(hi)); return r;
}
__device__ __forceinline__ void unpack2(u64 v, float &lo, float &hi) {
    asm("mov.b64 {%0, %1}, %2;" : "=f"(lo), "=f"(hi) : "l"(v));
}
__device__ __forceinline__ void fma2(u64 &d, u64 a, u64 b) {
    asm("fma.rn.f32x2 %0, %1, %2, %0;" : "+l"(d) : "l"(a), "l"(b));
}
__device__ __forceinline__ u64 fma2_3(u64 a, u64 b, u64 c) {
    u64 d; asm("fma.rn.f32x2 %0, %1, %2, %3;" : "=l"(d) : "l"(a), "l"(b), "l"(c)); return d;
}

// ---- activations ----
__device__ __forceinline__ float tanh_fast(float x) {
    float r; asm("tanh.approx.f32 %0, %1;" : "=f"(r) : "f"(x)); return r;
}
__device__ __forceinline__ float sig_fast(float x) {
    return fmaf(tanh_fast(0.5f * x), 0.5f, 0.5f);
}
__device__ __forceinline__ float sig_acc(float x) {
    return __fdividef(1.0f, 1.0f + __expf(-x));
}

__global__ void __launch_bounds__(128, 4)
lstm_disc_kernel(const float* __restrict__ values,
                 const float* __restrict__ masks,
                 const float* __restrict__ W_ih,   // (40,1)
                 const float* __restrict__ W_hh,   // (40,10) row-major
                 const float* __restrict__ b_ih,   // (40)
                 const float* __restrict__ b_hh,   // (40)
                 const float* __restrict__ W1,     // (5,10)
                 const float* __restrict__ b1,     // (5)
                 const float* __restrict__ W2,     // (1,5)
                 const float* __restrict__ b2,     // (1)
                 float* __restrict__ out,          // scores (B,T) then masks (B,T)
                 int B)
{
    // Gate-pair packed layouts. For lane-pair p (lanes 2p,2p+1) and h-index k:
    // sWg[p][k] = { Wi[2p],Wi[2p+1], Wf[2p],Wf[2p+1], Wg[2p],Wg[2p+1], Wo[2p],Wo[2p+1] }[k]
    __shared__ __align__(16) float sWg[5][Hd][8];
    // sBX[p][0..7] = bias pairs (same gate order), sBX[p][8..15] = W_ih pairs
    __shared__ __align__(16) float sBX[5][16];
    __shared__ __align__(8)  float2 sW1p[M1][M1];  // (W1[j][2q], W1[j][2q+1])
    __shared__ __align__(8)  float2 sB1p[M1];      // (b1[j], 0)
    __shared__ float sW2[M1];
    __shared__ float sB2;

    const int tid = threadIdx.x;
    for (int i = tid; i < 5 * Hd * 8; i += blockDim.x) {
        int p = i / 80, r = i % 80, k = r / 8, g = r % 8;
        int j = (g >> 1) * 10 + 2 * p + (g & 1);   // gate row index in [0,40)
        sWg[p][k][g] = W_hh[j * Hd + k];
    }
    for (int i = tid; i < 80; i += blockDim.x) {
        int p = i / 16, r = i % 16;
        int g = (r < 8) ? r : r - 8;
        int j = (g >> 1) * 10 + 2 * p + (g & 1);
        sBX[p][r] = (r < 8) ? (b_ih[j] + b_hh[j]) : W_ih[j];
    }
    if (tid < M1 * M1) {
        int j = tid / M1, q = tid % M1;
        sW1p[j][q] = make_float2(W1[j * Hd + 2 * q], W1[j * Hd + 2 * q + 1]);
    }
    if (tid < M1) { sB1p[tid] = make_float2(b1[tid], 0.0f); sW2[tid] = W2[tid]; }
    if (tid == 0) sB2 = b2[0];
    __syncthreads();

    const int tix = blockIdx.x * blockDim.x + tid;
    const int e0 = 2 * tix;                 // this thread owns elements e0, e0+1
    if (e0 >= B) return;

    const float4* __restrict__ v0 = (const float4*)(values + (size_t)e0 * Td);
    const float4* __restrict__ v1 = (const float4*)(values + (size_t)(e0 + 1) * Td);
    float4* __restrict__ s0 = (float4*)(out + (size_t)e0 * Td);
    float4* __restrict__ s1 = (float4*)(out + (size_t)(e0 + 1) * Td);

    float h0[Hd], c0[Hd], h1[Hd], c1[Hd];
#pragma unroll
    for (int k = 0; k < Hd; k++) { h0[k] = 0.f; c0[k] = 0.f; h1[k] = 0.f; c1[k] = 0.f; }

#pragma unroll 1
    for (int tb = 0; tb < Td / 4; tb++) {
        const float4 x40 = v0[tb];
        const float4 x41 = v1[tb];
        float sc0[4], sc1[4];

#pragma unroll
        for (int tt = 0; tt < 4; tt++) {
            const float x0 = (tt == 0) ? x40.x : (tt == 1) ? x40.y : (tt == 2) ? x40.z : x40.w;
            const float x1 = (tt == 0) ? x41.x : (tt == 1) ? x41.y : (tt == 2) ? x41.z : x41.w;

            // ---- MLP scoring head on pre-update h (weights shared across both elems) ----
            u64 hp0[M1], hp1[M1];
#pragma unroll
            for (int q = 0; q < M1; q++) {
                hp0[q] = pack2(h0[2 * q], h0[2 * q + 1]);
                hp1[q] = pack2(h1[2 * q], h1[2 * q + 1]);
            }
            float a0 = sB2, a1 = sB2;
#pragma unroll
            for (int j = 0; j < M1; j++) {
                const u64 bj = *(const u64*)&sB1p[j];
                u64 t0 = bj, t1 = bj;
#pragma unroll
                for (int q = 0; q < M1; q++) {
                    const u64 w = *(const u64*)&sW1p[j][q];
                    fma2(t0, hp0[q], w);
                    fma2(t1, hp1[q], w);
                }
                float lo, hi;
                unpack2(t0, lo, hi); float z0 = lo + hi; z0 = fmaxf(z0, 0.2f * z0);
                unpack2(t1, lo, hi); float z1 = lo + hi; z1 = fmaxf(z1, 0.2f * z1);
                const float w2j = sW2[j];
                a0 = fmaf(w2j, z0, a0);
                a1 = fmaf(w2j, z1, a1);
            }
            sc0[tt] = sig_acc(a0);
            sc1[tt] = sig_acc(a1);

            // ---- LSTM gates, p-block at a time (4 u64 accumulators per element) ----
            const u64 x0p = pack2(x0, x0), x1p = pack2(x1, x1);
            float hn0[Hd], hn1[Hd];
#pragma unroll
            for (int p = 0; p < 5; p++) {
                const ulonglong2* __restrict__ bx = (const ulonglong2*)sBX[p];
                const ulonglong2 bA = bx[0], bB = bx[1], wA = bx[2], wB = bx[3];
                u64 aI0 = fma2_3(x0p, wA.x, bA.x), aF0 = fma2_3(x0p, wA.y, bA.y);
                u64 aG0 = fma2_3(x0p, wB.x, bB.x), aO0 = fma2_3(x0p, wB.y, bB.y);
                u64 aI1 = fma2_3(x1p, wA.x, bA.x), aF1 = fma2_3(x1p, wA.y, bA.y);
                u64 aG1 = fma2_3(x1p, wB.x, bB.x), aO1 = fma2_3(x1p, wB.y, bB.y);

                const ulonglong2* __restrict__ wg = (const ulonglong2*)&sWg[p][0][0];
#pragma unroll
                for (int k = 0; k < Hd; k++) {
                    const ulonglong2 wIF = wg[2 * k];      // LDS.128: i-pair, f-pair
                    const ulonglong2 wGO = wg[2 * k + 1];  // LDS.128: g-pair, o-pair
                    const u64 hk0 = pack2(h0[k], h0[k]);
                    fma2(aI0, hk0, wIF.x); fma2(aF0, hk0, wIF.y);
                    fma2(aG0, hk0, wGO.x); fma2(aO0, hk0, wGO.y);
                    const u64 hk1 = pack2(h1[k], h1[k]);
                    fma2(aI1, hk1, wIF.x); fma2(aF1, hk1, wIF.y);
                    fma2(aG1, hk1, wGO.x); fma2(aO1, hk1, wGO.y);
                }

                float ia, ib, fa, fb, ga, gb, oa, ob;
                // element 0
                unpack2(aI0, ia, ib); unpack2(aF0, fa, fb);
                unpack2(aG0, ga, gb); unpack2(aO0, oa, ob);
                {
                    const float cnA = fmaf(sig_fast(fa), c0[2 * p],     sig_fast(ia) * tanh_fast(ga));
                    const float cnB = fmaf(sig_fast(fb), c0[2 * p + 1], sig_fast(ib) * tanh_fast(gb));
                    c0[2 * p] = cnA; c0[2 * p + 1] = cnB;
                    hn0[2 * p]     = sig_fast(oa) * tanh_fast(cnA);
                    hn0[2 * p + 1] = sig_fast(ob) * tanh_fast(cnB);
                }
                // element 1
                unpack2(aI1, ia, ib); unpack2(aF1, fa, fb);
                unpack2(aG1, ga, gb); unpack2(aO1, oa, ob);
                {
                    const float cnA = fmaf(sig_fast(fa), c1[2 * p],     sig_fast(ia) * tanh_fast(ga));
                    const float cnB = fmaf(sig_fast(fb), c1[2 * p + 1], sig_fast(ib) * tanh_fast(gb));
                    c1[2 * p] = cnA; c1[2 * p + 1] = cnB;
                    hn1[2 * p]     = sig_fast(oa) * tanh_fast(cnA);
                    hn1[2 * p + 1] = sig_fast(ob) * tanh_fast(cnB);
                }
            }
#pragma unroll
            for (int k = 0; k < Hd; k++) { h0[k] = hn0[k]; h1[k] = hn1[k]; }
        }

        s0[tb] = make_float4(sc0[0], sc0[1], sc0[2], sc0[3]);
        s1[tb] = make_float4(sc1[0], sc1[1], sc1[2], sc1[3]);
    }

    // ---- masks passthrough: 2 contiguous rows = 40 floats = 10 float4 ----
    const float4* __restrict__ m0 = (const float4*)(masks + (size_t)e0 * Td);
    float4* __restrict__ mo = (float4*)(out + (size_t)B * Td + (size_t)e0 * Td);
#pragma unroll
    for (int q = 0; q < 2 * Td / 4; q++) mo[q] = m0[q];
}

extern "C" void kernel_launch(void* const* d_in, const int* in_sizes, int n_in,
                              void* d_out, int out_size)
{
    const float* values = (const float*)d_in[0];
    const float* masks  = (const float*)d_in[1];
    const float* W_ih   = (const float*)d_in[2];
    const float* W_hh   = (const float*)d_in[3];
    const float* b_ih   = (const float*)d_in[4];
    const float* b_hh   = (const float*)d_in[5];
    const float* W1     = (const float*)d_in[6];
    const float* b1     = (const float*)d_in[7];
    const float* W2     = (const float*)d_in[8];
    const float* b2     = (const float*)d_in[9];

    const int BT = in_sizes[0];          // B*T
    const int B  = BT / Td;
    float* out = (float*)d_out;

    const int nthreads = B / 2;          // B is even (262144)
    lstm_disc_kernel<<<(nthreads + 127) / 128, 128>>>(
        values, masks, W_ih, W_hh, b_ih, b_hh, W1, b1, W2, b2, out, B);
}